// round 5
// baseline (speedup 1.0000x reference)
#include <cuda_runtime.h>
#include <cuda_bf16.h>
#include <cstdint>

// Problem shapes
#define B_ 16
#define T_ 24
#define N_ 512
#define D_ 128
#define Z_ 12
#define NEG_SLOPE 0.01f

#define MROWS 64           // rows per CTA -> grid 128
#define ASTRIDE 272        // 128 bf16 = 256B + 16B pad (4-bank row shift)

// smem byte offsets
#define OFF_AH 0
#define OFF_AL (64 * ASTRIDE)                 // 17408
#define OFF_B0 (128 * ASTRIDE)                // 34816
#define OFF_B1 (OFF_B0 + 256 * ASTRIDE)       // 104448
#define BLO    (128 * ASTRIDE)                // lo-half offset inside a B buffer
#define SMEM_BYTES (OFF_B1 + 256 * ASTRIDE)   // 174080
#define YSTRIDE 132                            // Ys[64][132] reuses A region

// pre-split W1: [chunk][row 0-127 = hi, 128-255 = lo][k]
__device__ __nv_bfloat16 W1S[3][256][128];

__device__ __forceinline__ uint32_t smem_u32(const void* p) {
    uint32_t a;
    asm("{ .reg .u64 t; cvta.to.shared.u64 t, %1; cvt.u32.u64 %0, t; }" : "=r"(a) : "l"(p));
    return a;
}
__device__ __forceinline__ uint32_t pack_hi(float a, float b, float& ra, float& rb) {
    __nv_bfloat16 ha = __float2bfloat16(a), hb = __float2bfloat16(b);
    ra = a - __bfloat162float(ha);
    rb = b - __bfloat162float(hb);
    __nv_bfloat162 p; p.x = ha; p.y = hb;
    return *reinterpret_cast<uint32_t*>(&p);
}
__device__ __forceinline__ uint32_t pack_lo(float a, float b) {
    __nv_bfloat16 ha = __float2bfloat16(a), hb = __float2bfloat16(b);
    __nv_bfloat162 p; p.x = ha; p.y = hb;
    return *reinterpret_cast<uint32_t*>(&p);
}
__device__ __forceinline__ void mma16816(float* c, const uint32_t* a, uint32_t b0, uint32_t b1) {
    asm volatile(
        "mma.sync.aligned.m16n8k16.row.col.f32.bf16.bf16.f32 "
        "{%0,%1,%2,%3},{%4,%5,%6,%7},{%8,%9},{%0,%1,%2,%3};"
        : "+f"(c[0]), "+f"(c[1]), "+f"(c[2]), "+f"(c[3])
        : "r"(a[0]), "r"(a[1]), "r"(a[2]), "r"(a[3]), "r"(b0), "r"(b1));
}
#define LDSM4(r, a) asm volatile(                                              \
    "ldmatrix.sync.aligned.m8n8.x4.shared.b16 {%0,%1,%2,%3}, [%4];"            \
    : "=r"((r)[0]), "=r"((r)[1]), "=r"((r)[2]), "=r"((r)[3]) : "r"(a))
__device__ __forceinline__ void cp_async16(uint32_t dst, const void* src) {
    asm volatile("cp.async.cg.shared.global [%0], [%1], 16;" :: "r"(dst), "l"(src) : "memory");
}
#define CP_COMMIT() asm volatile("cp.async.commit_group;" ::: "memory")
#define CP_WAIT(n)  asm volatile("cp.async.wait_group %0;" :: "n"(n) : "memory")

// ---- prep kernel: split W1 fp32 -> hi/lo bf16, chunked layout ----
__global__ void prep_w1_kernel(const float* __restrict__ W1) {
    int idx4 = blockIdx.x * 256 + threadIdx.x;   // 0..12287
    int idx = idx4 * 4;                          // element index, 0..49151
    int c = idx / 16384;
    int rem = idx - c * 16384;
    int n = rem >> 7;
    int k = rem & 127;
    float4 v = *reinterpret_cast<const float4*>(W1 + (size_t)n * 384 + c * 128 + k);
    float r0, r1, r2, r3;
    uint32_t h01 = pack_hi(v.x, v.y, r0, r1);
    uint32_t h23 = pack_hi(v.z, v.w, r2, r3);
    *reinterpret_cast<uint2*>(&W1S[c][n][k])       = make_uint2(h01, h23);
    *reinterpret_cast<uint2*>(&W1S[c][128 + n][k]) =
        make_uint2(pack_lo(r0, r1), pack_lo(r2, r3));
}

__global__ void __launch_bounds__(256)
fusion_mma_kernel(const float* __restrict__ Ht,
                  const float* __restrict__ Hs,
                  const float* __restrict__ Hm,
                  const float* __restrict__ b1,   // [128]
                  const float* __restrict__ W2,   // [12][128]
                  const float* __restrict__ b2,   // [12]
                  float* __restrict__ out)        // [16][12][512]
{
    extern __shared__ char smem[];
    const uint32_t sb = smem_u32(smem);
    const int tid  = threadIdx.x;
    const int wid  = tid >> 5;
    const int lane = tid & 31;
    const int g    = lane >> 2;
    const int t    = lane & 3;
    const int warpM = wid >> 1;      // rows warpM*16
    const int warpN = wid & 1;       // cols warpN*64
    const int rowBase = blockIdx.x * MROWS;

    const float* segs[3] = {Ht, Hs, Hm};

    float acc[8][4];
    #pragma unroll
    for (int j = 0; j < 8; ++j)
        #pragma unroll
        for (int i = 0; i < 4; ++i) acc[j][i] = 0.f;

    // fragment base addresses (ldmatrix lane addressing)
    const uint32_t aHi = sb + OFF_AH + (uint32_t)((warpM * 16 + (lane & 15)) * ASTRIDE)
                       + (uint32_t)((lane >> 4) * 16);
    const uint32_t aLo = aHi + OFF_AL;
    const uint32_t bRowOff = (uint32_t)((warpN * 64 + (lane & 7) + ((lane & 16) >> 1)) * ASTRIDE)
                           + (uint32_t)((lane & 8) << 1);

    // ---- cp.async B loader ----
    auto ldB = [&](int c, uint32_t bufOff) {
        const char* src = reinterpret_cast<const char*>(&W1S[c][0][0]);
        #pragma unroll
        for (int i = 0; i < 16; ++i) {
            int idx = i * 256 + tid;             // 0..4095 (16B units)
            int row = idx >> 4, c16 = idx & 15;
            cp_async16(sb + bufOff + row * ASTRIDE + c16 * 16, src + (size_t)idx * 16);
        }
    };
    // ---- A prefetch (regs) + convert/STS ----
    float4 regA[8];
    auto ldA = [&](int c) {
        const float* src = segs[c];
        #pragma unroll
        for (int i = 0; i < 8; ++i) {
            int idx = i * 256 + tid;
            int r = idx >> 5, f4 = idx & 31;
            int grp = rowBase + r;
            int b = grp >> 9, n = grp & 511;
            regA[i] = *reinterpret_cast<const float4*>(
                src + (((size_t)b * T_ + (T_ - 1)) * N_ + n) * D_ + f4 * 4);
        }
    };
    auto stsA = [&]() {
        #pragma unroll
        for (int i = 0; i < 8; ++i) {
            int idx = i * 256 + tid;
            int r = idx >> 5, f4 = idx & 31;
            float4 v = regA[i];
            float r0, r1, r2, r3;
            uint32_t h01 = pack_hi(v.x, v.y, r0, r1);
            uint32_t h23 = pack_hi(v.z, v.w, r2, r3);
            *reinterpret_cast<uint2*>(smem + OFF_AH + r * ASTRIDE + f4 * 8) = make_uint2(h01, h23);
            *reinterpret_cast<uint2*>(smem + OFF_AL + r * ASTRIDE + f4 * 8) =
                make_uint2(pack_lo(r0, r1), pack_lo(r2, r3));
        }
    };
    // ---- one K chunk of MMAs from B buffer at bufOff ----
    auto mmaChunk = [&](uint32_t bufOff) {
        const uint32_t bB = sb + bufOff + bRowOff;
        #pragma unroll
        for (int kk = 0; kk < 8; ++kk) {
            uint32_t ah[4], al[4];
            LDSM4(ah, aHi + kk * 32);
            LDSM4(al, aLo + kk * 32);
            #pragma unroll
            for (int p = 0; p < 4; ++p) {
                uint32_t bh[4], bl[4];
                uint32_t ba = bB + p * (16 * ASTRIDE) + kk * 32;
                LDSM4(bh, ba);
                LDSM4(bl, ba + BLO);
                mma16816(acc[2*p],   ah, bh[0], bh[1]);
                mma16816(acc[2*p],   ah, bl[0], bl[1]);
                mma16816(acc[2*p],   al, bh[0], bh[1]);
                mma16816(acc[2*p+1], ah, bh[2], bh[3]);
                mma16816(acc[2*p+1], ah, bl[2], bl[3]);
                mma16816(acc[2*p+1], al, bh[2], bh[3]);
            }
        }
    };

    // ---- prologue ----
    ldB(0, OFF_B0); CP_COMMIT();
    ldA(0);
    stsA();
    ldB(1, OFF_B1); CP_COMMIT();
    CP_WAIT(1);                 // B0 arrived
    __syncthreads();

    // ---- chunk 0 ----
    ldA(1);                     // overlaps MMA
    mmaChunk(OFF_B0);
    __syncthreads();
    ldB(2, OFF_B0); CP_COMMIT();
    stsA();                     // A chunk 1
    CP_WAIT(1);                 // B1 arrived
    __syncthreads();

    // ---- chunk 1 ----
    ldA(2);
    mmaChunk(OFF_B1);
    __syncthreads();
    stsA();                     // A chunk 2
    CP_WAIT(0);                 // B2 arrived
    __syncthreads();

    // ---- chunk 2 ----
    mmaChunk(OFF_B0);
    __syncthreads();            // all warps done reading A region before Ys reuse

    // ---- epilogue: bias + LeakyReLU -> Ys (reuses A region) ----
    float* Ys = reinterpret_cast<float*>(smem);
    #pragma unroll
    for (int j = 0; j < 8; ++j) {
        int col = warpN * 64 + j * 8 + 2 * t;
        float bv0 = __ldg(b1 + col), bv1 = __ldg(b1 + col + 1);
        int row0 = warpM * 16 + g;
        float y0 = acc[j][0] + bv0; y0 = (y0 > 0.f) ? y0 : NEG_SLOPE * y0;
        float y1 = acc[j][1] + bv1; y1 = (y1 > 0.f) ? y1 : NEG_SLOPE * y1;
        float y2 = acc[j][2] + bv0; y2 = (y2 > 0.f) ? y2 : NEG_SLOPE * y2;
        float y3 = acc[j][3] + bv1; y3 = (y3 > 0.f) ? y3 : NEG_SLOPE * y3;
        *reinterpret_cast<float2*>(Ys + row0 * YSTRIDE + col)       = make_float2(y0, y1);
        *reinterpret_cast<float2*>(Ys + (row0 + 8) * YSTRIDE + col) = make_float2(y2, y3);
    }
    __syncthreads();

    // ---- GEMM2: 64 rows x 12 z, 3 outputs/thread ----
    #pragma unroll
    for (int it = 0; it < 3; ++it) {
        int o = it * 256 + tid;
        int r = o / Z_, z = o - r * Z_;
        float s = __ldg(b2 + z);
        const float4* w = reinterpret_cast<const float4*>(W2 + (size_t)z * D_);
        const float4* y = reinterpret_cast<const float4*>(Ys + r * YSTRIDE);
        #pragma unroll 8
        for (int d4 = 0; d4 < 32; ++d4) {
            float4 wv = __ldg(w + d4);
            float4 yv = y[d4];
            s += yv.x * wv.x + yv.y * wv.y + yv.z * wv.z + yv.w * wv.w;
        }
        int grp = rowBase + r;
        int b = grp >> 9, n = grp & 511;
        out[((size_t)b * Z_ + z) * N_ + n] = s;
    }
}

extern "C" void kernel_launch(void* const* d_in, const int* in_sizes, int n_in,
                              void* d_out, int out_size)
{
    const float* Ht = (const float*)d_in[0];
    const float* Hs = (const float*)d_in[1];
    const float* Hm = (const float*)d_in[2];
    const float* W1 = (const float*)d_in[3];
    const float* b1 = (const float*)d_in[4];
    const float* W2 = (const float*)d_in[5];
    const float* b2 = (const float*)d_in[6];
    float* out = (float*)d_out;

    prep_w1_kernel<<<48, 256>>>(W1);

    cudaFuncSetAttribute(fusion_mma_kernel,
                         cudaFuncAttributeMaxDynamicSharedMemorySize, SMEM_BYTES);
    int grid = (B_ * N_) / MROWS;   // 128 CTAs
    fusion_mma_kernel<<<grid, 256, SMEM_BYTES>>>(Ht, Hs, Hm, b1, W2, b2, out);
}

// round 6
// speedup vs baseline: 1.5219x; 1.5219x over previous
#include <cuda_runtime.h>
#include <cuda_bf16.h>
#include <cstdint>

// Problem shapes
#define B_ 16
#define T_ 24
#define N_ 512
#define D_ 128
#define Z_ 12
#define NEG_SLOPE 0.01f

#define MROWS 32           // rows per CTA -> grid 256, 2 CTAs/SM
#define NCHUNK 3           // K chunks of 128 (= one source segment each)

// smem: bf16 tiles with 272-byte padded rows (4-bank row shift, conflict-free)
#define ASTRIDE 272
#define OFF_AH  0
#define OFF_AL  (32 * ASTRIDE)                  // 8704
#define OFF_BH  (2 * 32 * ASTRIDE)              // 17408
#define OFF_BL  (OFF_BH + 128 * ASTRIDE)        // 52224
#define SMEM_BYTES (OFF_BH + 2 * 128 * ASTRIDE) // 87040
#define YSTRIDE 132        // Ys[32][132] floats = 16896B, reuses A region (17408B)

__device__ __forceinline__ uint32_t pack_hi(float a, float b, float& ra, float& rb) {
    __nv_bfloat16 ha = __float2bfloat16(a), hb = __float2bfloat16(b);
    ra = a - __bfloat162float(ha);
    rb = b - __bfloat162float(hb);
    __nv_bfloat162 p; p.x = ha; p.y = hb;
    return *reinterpret_cast<uint32_t*>(&p);
}
__device__ __forceinline__ uint32_t pack_lo(float a, float b) {
    __nv_bfloat16 ha = __float2bfloat16(a), hb = __float2bfloat16(b);
    __nv_bfloat162 p; p.x = ha; p.y = hb;
    return *reinterpret_cast<uint32_t*>(&p);
}
__device__ __forceinline__ void mma16816(float* c, const uint32_t* a, uint32_t b0, uint32_t b1) {
    asm volatile(
        "mma.sync.aligned.m16n8k16.row.col.f32.bf16.bf16.f32 "
        "{%0,%1,%2,%3},{%4,%5,%6,%7},{%8,%9},{%0,%1,%2,%3};"
        : "+f"(c[0]), "+f"(c[1]), "+f"(c[2]), "+f"(c[3])
        : "r"(a[0]), "r"(a[1]), "r"(a[2]), "r"(a[3]), "r"(b0), "r"(b1));
}

__global__ void __launch_bounds__(256, 2)
fusion_mma_kernel(const float* __restrict__ Ht,
                  const float* __restrict__ Hs,
                  const float* __restrict__ Hm,
                  const float* __restrict__ W1,   // [128][384]
                  const float* __restrict__ b1,   // [128]
                  const float* __restrict__ W2,   // [12][128]
                  const float* __restrict__ b2,   // [12]
                  float* __restrict__ out)        // [16][12][512]
{
    extern __shared__ char smem[];
    const int tid  = threadIdx.x;
    const int wid  = tid >> 5;
    const int lane = tid & 31;
    const int g    = lane >> 2;      // group id 0..7
    const int t    = lane & 3;       // thread-in-group
    const int warpM = wid >> 2;      // 0..1 -> rows warpM*16
    const int warpN = wid & 3;       // 0..3 -> cols warpN*32
    const int rowBase = blockIdx.x * MROWS;

    const float* segs[3] = {Ht, Hs, Hm};

    float acc[4][4];
    #pragma unroll
    for (int j = 0; j < 4; ++j)
        #pragma unroll
        for (int i = 0; i < 4; ++i) acc[j][i] = 0.f;

    // prefetch A chunk 0 into regs: 4 float4/thread (32 rows x 32 float4)
    float4 regA[4];
    #pragma unroll
    for (int i = 0; i < 4; ++i) {
        int idx = i * 256 + tid;
        int r = idx >> 5, f4 = idx & 31;
        int grp = rowBase + r;
        int b = grp >> 9, n = grp & 511;
        regA[i] = *reinterpret_cast<const float4*>(
            segs[0] + (((size_t)b * T_ + (T_ - 1)) * N_ + n) * D_ + f4 * 4);
    }

    #pragma unroll
    for (int c = 0; c < NCHUNK; ++c) {
        // ---- STS A chunk (hi/lo split) from prefetched regs ----
        #pragma unroll
        for (int i = 0; i < 4; ++i) {
            int idx = i * 256 + tid;
            int r = idx >> 5, f4 = idx & 31;
            float4 v = regA[i];
            float r0, r1, r2, r3;
            uint32_t h01 = pack_hi(v.x, v.y, r0, r1);
            uint32_t h23 = pack_hi(v.z, v.w, r2, r3);
            *reinterpret_cast<uint2*>(smem + OFF_AH + r * ASTRIDE + f4 * 8) = make_uint2(h01, h23);
            *reinterpret_cast<uint2*>(smem + OFF_AL + r * ASTRIDE + f4 * 8) =
                make_uint2(pack_lo(r0, r1), pack_lo(r2, r3));
        }
        // ---- load + split + STS B chunk: W1 cols [c*128, c*128+128) ----
        #pragma unroll
        for (int i = 0; i < 16; ++i) {
            int idx = i * 256 + tid;
            int n = idx >> 5, f4 = idx & 31;
            float4 v = *reinterpret_cast<const float4*>(W1 + (size_t)n * 384 + c * 128 + f4 * 4);
            float r0, r1, r2, r3;
            uint32_t h01 = pack_hi(v.x, v.y, r0, r1);
            uint32_t h23 = pack_hi(v.z, v.w, r2, r3);
            *reinterpret_cast<uint2*>(smem + OFF_BH + n * ASTRIDE + f4 * 8) = make_uint2(h01, h23);
            *reinterpret_cast<uint2*>(smem + OFF_BL + n * ASTRIDE + f4 * 8) =
                make_uint2(pack_lo(r0, r1), pack_lo(r2, r3));
        }
        __syncthreads();

        // prefetch next A chunk (overlaps with MMA below)
        if (c < NCHUNK - 1) {
            const float* src = segs[c + 1];
            #pragma unroll
            for (int i = 0; i < 4; ++i) {
                int idx = i * 256 + tid;
                int r = idx >> 5, f4 = idx & 31;
                int grp = rowBase + r;
                int b = grp >> 9, n = grp & 511;
                regA[i] = *reinterpret_cast<const float4*>(
                    src + (((size_t)b * T_ + (T_ - 1)) * N_ + n) * D_ + f4 * 4);
            }
        }

        // ---- MMA: 8 k16-steps, 4 n-tiles, 3 terms ----
        const char* Abase = smem + (warpM * 16 + g) * ASTRIDE + t * 4;
        const char* Bbase = smem + (warpN * 32 + g) * ASTRIDE + t * 4;
        #pragma unroll
        for (int kk = 0; kk < 8; ++kk) {
            uint32_t ah[4], al[4];
            const char* pa = Abase + kk * 32;
            ah[0] = *reinterpret_cast<const uint32_t*>(pa + OFF_AH);
            ah[1] = *reinterpret_cast<const uint32_t*>(pa + OFF_AH + 8 * ASTRIDE);
            ah[2] = *reinterpret_cast<const uint32_t*>(pa + OFF_AH + 16);
            ah[3] = *reinterpret_cast<const uint32_t*>(pa + OFF_AH + 8 * ASTRIDE + 16);
            al[0] = *reinterpret_cast<const uint32_t*>(pa + OFF_AL);
            al[1] = *reinterpret_cast<const uint32_t*>(pa + OFF_AL + 8 * ASTRIDE);
            al[2] = *reinterpret_cast<const uint32_t*>(pa + OFF_AL + 16);
            al[3] = *reinterpret_cast<const uint32_t*>(pa + OFF_AL + 8 * ASTRIDE + 16);
            #pragma unroll
            for (int j = 0; j < 4; ++j) {
                const char* pb = Bbase + j * 8 * ASTRIDE + kk * 32;
                uint32_t bh0 = *reinterpret_cast<const uint32_t*>(pb + OFF_BH);
                uint32_t bh1 = *reinterpret_cast<const uint32_t*>(pb + OFF_BH + 16);
                uint32_t bl0 = *reinterpret_cast<const uint32_t*>(pb + OFF_BL);
                uint32_t bl1 = *reinterpret_cast<const uint32_t*>(pb + OFF_BL + 16);
                mma16816(acc[j], ah, bh0, bh1);   // hi*hi
                mma16816(acc[j], ah, bl0, bl1);   // hi*lo
                mma16816(acc[j], al, bh0, bh1);   // lo*hi
            }
        }
        __syncthreads();
    }

    // ---- epilogue: bias + LeakyReLU -> Ys smem (reuses A region) ----
    float* Ys = reinterpret_cast<float*>(smem);
    #pragma unroll
    for (int j = 0; j < 4; ++j) {
        int col = warpN * 32 + j * 8 + 2 * t;
        float bv0 = __ldg(b1 + col), bv1 = __ldg(b1 + col + 1);
        int row0 = warpM * 16 + g;
        float y0 = acc[j][0] + bv0; y0 = (y0 > 0.f) ? y0 : NEG_SLOPE * y0;
        float y1 = acc[j][1] + bv1; y1 = (y1 > 0.f) ? y1 : NEG_SLOPE * y1;
        float y2 = acc[j][2] + bv0; y2 = (y2 > 0.f) ? y2 : NEG_SLOPE * y2;
        float y3 = acc[j][3] + bv1; y3 = (y3 > 0.f) ? y3 : NEG_SLOPE * y3;
        *reinterpret_cast<float2*>(Ys + row0 * YSTRIDE + col)       = make_float2(y0, y1);
        *reinterpret_cast<float2*>(Ys + (row0 + 8) * YSTRIDE + col) = make_float2(y2, y3);
    }
    __syncthreads();

    // ---- GEMM2: 32 rows x 12 z = 384 outputs ----
    #pragma unroll
    for (int it = 0; it < 2; ++it) {
        int o = it * 256 + tid;
        if (o < MROWS * Z_) {
            int r = o / Z_, z = o - r * Z_;
            float s = __ldg(b2 + z);
            const float4* w = reinterpret_cast<const float4*>(W2 + (size_t)z * D_);
            const float4* y = reinterpret_cast<const float4*>(Ys + r * YSTRIDE);
            #pragma unroll 8
            for (int d4 = 0; d4 < 32; ++d4) {
                float4 wv = __ldg(w + d4);
                float4 yv = y[d4];
                s += yv.x * wv.x + yv.y * wv.y + yv.z * wv.z + yv.w * wv.w;
            }
            int grp = rowBase + r;
            int b = grp >> 9, n = grp & 511;
            out[((size_t)b * Z_ + z) * N_ + n] = s;
        }
    }
}

extern "C" void kernel_launch(void* const* d_in, const int* in_sizes, int n_in,
                              void* d_out, int out_size)
{
    const float* Ht = (const float*)d_in[0];
    const float* Hs = (const float*)d_in[1];
    const float* Hm = (const float*)d_in[2];
    const float* W1 = (const float*)d_in[3];
    const float* b1 = (const float*)d_in[4];
    const float* W2 = (const float*)d_in[5];
    const float* b2 = (const float*)d_in[6];
    float* out = (float*)d_out;

    cudaFuncSetAttribute(fusion_mma_kernel,
                         cudaFuncAttributeMaxDynamicSharedMemorySize, SMEM_BYTES);

    int grid = (B_ * N_) / MROWS;   // 256 CTAs
    fusion_mma_kernel<<<grid, 256, SMEM_BYTES>>>(Ht, Hs, Hm, W1, b1, W2, b2, out);
}

// round 7
// speedup vs baseline: 1.5328x; 1.0072x over previous
#include <cuda_runtime.h>
#include <cuda_bf16.h>
#include <cstdint>

// Problem shapes
#define B_ 16
#define T_ 24
#define N_ 512
#define D_ 128
#define Z_ 12
#define NEG_SLOPE 0.01f

#define MROWS 32           // rows per CTA -> grid 256
#define NCHUNK 3           // K chunks of 128

// interleaved hi/lo layout: per row, per kk(16 k): 8 x [hi_pair(u32), lo_pair(u32)]
// row bytes = 128 k * 4B(pair hi+lo)/2 ... = 512B data, stride 544 (8-bank row shift)
#define RSTRIDE 544
#define OFF_A 0
#define OFF_B (32 * RSTRIDE)                    // 17408
#define SMEM_BYTES (OFF_B + 128 * RSTRIDE)      // 87040
#define YSTRIDE 132        // Ys[32][132] floats = 16896B, fits in A region

// split pair (a,b) -> hi bf16x2 (truncated) + lo bf16x2 (residual, truncated)
__device__ __forceinline__ uint32_t split_pair(float a, float b, uint32_t& lo) {
    uint32_t ia = __float_as_uint(a), ib = __float_as_uint(b);
    uint32_t hi = __byte_perm(ia, ib, 0x7632);
    float ra = a - __uint_as_float(ia & 0xFFFF0000u);
    float rb = b - __uint_as_float(ib & 0xFFFF0000u);
    lo = __byte_perm(__float_as_uint(ra), __float_as_uint(rb), 0x7632);
    return hi;
}

__device__ __forceinline__ void mma16816(float* c, const uint32_t* a, uint32_t b0, uint32_t b1) {
    asm volatile(
        "mma.sync.aligned.m16n8k16.row.col.f32.bf16.bf16.f32 "
        "{%0,%1,%2,%3},{%4,%5,%6,%7},{%8,%9},{%0,%1,%2,%3};"
        : "+f"(c[0]), "+f"(c[1]), "+f"(c[2]), "+f"(c[3])
        : "r"(a[0]), "r"(a[1]), "r"(a[2]), "r"(a[3]), "r"(b0), "r"(b1));
}

__global__ void __launch_bounds__(256, 2)
fusion_mma_kernel(const float* __restrict__ Ht,
                  const float* __restrict__ Hs,
                  const float* __restrict__ Hm,
                  const float* __restrict__ W1,   // [128][384]
                  const float* __restrict__ b1,   // [128]
                  const float* __restrict__ W2,   // [12][128]
                  const float* __restrict__ b2,   // [12]
                  float* __restrict__ out)        // [16][12][512]
{
    extern __shared__ char smem[];
    const int tid  = threadIdx.x;
    const int wid  = tid >> 5;
    const int lane = tid & 31;
    const int g    = lane >> 2;      // 0..7
    const int t    = lane & 3;       // 0..3
    const int wm   = wid >> 2;       // 0..1 -> rows wm*16
    const int wn   = wid & 3;        // 0..3 -> cols wn*32
    const int rowBase = blockIdx.x * MROWS;

    const float* segs[3] = {Ht, Hs, Hm};

    float acc[4][4];
    #pragma unroll
    for (int j = 0; j < 4; ++j)
        #pragma unroll
        for (int i = 0; i < 4; ++i) acc[j][i] = 0.f;

    // prefetch A chunk 0: 4 float4/thread (32 rows x 32 float4)
    float4 regA[4];
    #pragma unroll
    for (int i = 0; i < 4; ++i) {
        int idx = i * 256 + tid;
        int r = idx >> 5, f4 = idx & 31;
        int grp = rowBase + r;
        int b = grp >> 9, n = grp & 511;
        regA[i] = *reinterpret_cast<const float4*>(
            segs[0] + (((size_t)b * T_ + (T_ - 1)) * N_ + n) * D_ + f4 * 4);
    }

    // fragment base addresses
    const char* Ab = smem + OFF_A + (wm * 16 + g) * RSTRIDE + t * 8;
    const char* Bb = smem + OFF_B + (wn * 32 + g) * RSTRIDE + t * 8;

    #pragma unroll
    for (int c = 0; c < NCHUNK; ++c) {
        // ---- STS A chunk from prefetched regs (interleaved hi/lo, STS.128) ----
        #pragma unroll
        for (int i = 0; i < 4; ++i) {
            int idx = i * 256 + tid;
            int r = idx >> 5, f4 = idx & 31;
            float4 v = regA[i];
            uint32_t l01, l23;
            uint32_t h01 = split_pair(v.x, v.y, l01);
            uint32_t h23 = split_pair(v.z, v.w, l23);
            *reinterpret_cast<uint4*>(smem + OFF_A + r * RSTRIDE + (f4 >> 2) * 64 + (f4 & 3) * 16)
                = make_uint4(h01, l01, h23, l23);
        }
        // ---- LDG + split + STS B chunk: W1 cols [c*128, c*128+128) ----
        #pragma unroll
        for (int i = 0; i < 16; ++i) {
            int idx = i * 256 + tid;
            int n = idx >> 5, f4 = idx & 31;
            float4 v = *reinterpret_cast<const float4*>(W1 + (size_t)n * 384 + c * 128 + f4 * 4);
            uint32_t l01, l23;
            uint32_t h01 = split_pair(v.x, v.y, l01);
            uint32_t h23 = split_pair(v.z, v.w, l23);
            *reinterpret_cast<uint4*>(smem + OFF_B + n * RSTRIDE + (f4 >> 2) * 64 + (f4 & 3) * 16)
                = make_uint4(h01, l01, h23, l23);
        }
        __syncthreads();

        // prefetch next A chunk (overlaps MMA)
        if (c < NCHUNK - 1) {
            const float* src = segs[c + 1];
            #pragma unroll
            for (int i = 0; i < 4; ++i) {
                int idx = i * 256 + tid;
                int r = idx >> 5, f4 = idx & 31;
                int grp = rowBase + r;
                int b = grp >> 9, n = grp & 511;
                regA[i] = *reinterpret_cast<const float4*>(
                    src + (((size_t)b * T_ + (T_ - 1)) * N_ + n) * D_ + f4 * 4);
            }
        }

        // ---- MMA: 8 k16-steps x 4 n-tiles x 3 terms ----
        #pragma unroll
        for (int kk = 0; kk < 8; ++kk) {
            uint2 qa0 = *reinterpret_cast<const uint2*>(Ab + kk * 64);
            uint2 qa1 = *reinterpret_cast<const uint2*>(Ab + kk * 64 + 8 * RSTRIDE);
            uint2 qa2 = *reinterpret_cast<const uint2*>(Ab + kk * 64 + 32);
            uint2 qa3 = *reinterpret_cast<const uint2*>(Ab + kk * 64 + 8 * RSTRIDE + 32);
            uint32_t ah[4] = {qa0.x, qa1.x, qa2.x, qa3.x};
            uint32_t al[4] = {qa0.y, qa1.y, qa2.y, qa3.y};
            #pragma unroll
            for (int j = 0; j < 4; ++j) {
                uint2 qb0 = *reinterpret_cast<const uint2*>(Bb + j * 8 * RSTRIDE + kk * 64);
                uint2 qb1 = *reinterpret_cast<const uint2*>(Bb + j * 8 * RSTRIDE + kk * 64 + 32);
                mma16816(acc[j], ah, qb0.x, qb1.x);   // hi*hi
                mma16816(acc[j], ah, qb0.y, qb1.y);   // hi*lo
                mma16816(acc[j], al, qb0.x, qb1.x);   // lo*hi
            }
        }
        __syncthreads();
    }

    // ---- epilogue: bias + LeakyReLU -> Ys smem (reuses A region) ----
    float* Ys = reinterpret_cast<float*>(smem);
    #pragma unroll
    for (int j = 0; j < 4; ++j) {
        int col = wn * 32 + j * 8 + 2 * t;
        float bv0 = __ldg(b1 + col), bv1 = __ldg(b1 + col + 1);
        int row0 = wm * 16 + g;
        float y0 = acc[j][0] + bv0; y0 = (y0 > 0.f) ? y0 : NEG_SLOPE * y0;
        float y1 = acc[j][1] + bv1; y1 = (y1 > 0.f) ? y1 : NEG_SLOPE * y1;
        float y2 = acc[j][2] + bv0; y2 = (y2 > 0.f) ? y2 : NEG_SLOPE * y2;
        float y3 = acc[j][3] + bv1; y3 = (y3 > 0.f) ? y3 : NEG_SLOPE * y3;
        *reinterpret_cast<float2*>(Ys + row0 * YSTRIDE + col)       = make_float2(y0, y1);
        *reinterpret_cast<float2*>(Ys + (row0 + 8) * YSTRIDE + col) = make_float2(y2, y3);
    }
    __syncthreads();

    // ---- GEMM2: 32 rows x 12 z = 384 outputs ----
    #pragma unroll
    for (int it = 0; it < 2; ++it) {
        int o = it * 256 + tid;
        if (o < MROWS * Z_) {
            int r = o / Z_, z = o - r * Z_;
            float s = __ldg(b2 + z);
            const float4* w = reinterpret_cast<const float4*>(W2 + (size_t)z * D_);
            const float4* y = reinterpret_cast<const float4*>(Ys + r * YSTRIDE);
            #pragma unroll 8
            for (int d4 = 0; d4 < 32; ++d4) {
                float4 wv = __ldg(w + d4);
                float4 yv = y[d4];
                s += yv.x * wv.x + yv.y * wv.y + yv.z * wv.z + yv.w * wv.w;
            }
            int grp = rowBase + r;
            int b = grp >> 9, n = grp & 511;
            out[((size_t)b * Z_ + z) * N_ + n] = s;
        }
    }
}

extern "C" void kernel_launch(void* const* d_in, const int* in_sizes, int n_in,
                              void* d_out, int out_size)
{
    const float* Ht = (const float*)d_in[0];
    const float* Hs = (const float*)d_in[1];
    const float* Hm = (const float*)d_in[2];
    const float* W1 = (const float*)d_in[3];
    const float* b1 = (const float*)d_in[4];
    const float* W2 = (const float*)d_in[5];
    const float* b2 = (const float*)d_in[6];
    float* out = (float*)d_out;

    cudaFuncSetAttribute(fusion_mma_kernel,
                         cudaFuncAttributeMaxDynamicSharedMemorySize, SMEM_BYTES);

    int grid = (B_ * N_) / MROWS;   // 256 CTAs
    fusion_mma_kernel<<<grid, 256, SMEM_BYTES>>>(Ht, Hs, Hm, W1, b1, W2, b2, out);
}